// round 17
// baseline (speedup 1.0000x reference)
#include <cuda_runtime.h>
#include <cstdint>

// Problem shape (fixed for this dataset entry)
#define B_    2
#define N_    50000
#define C_    64
#define M_    50000
#define K_    16
#define H_    8
#define CMID_ 16

// Runtime-detected index width flag (int64 vs int32), set by detect kernel.
__device__ int g_idx_is64;

__global__ void detect_idx_kernel(const unsigned int* __restrict__ w) {
    if (threadIdx.x == 0 && blockIdx.x == 0) {
        int is64 = 1;
        #pragma unroll 1
        for (int i = 0; i < 256; i++) {
            if (w[2 * i + 1] != 0u) { is64 = 0; break; }
        }
        g_idx_is64 = is64;
    }
}

// TWO points per WARP (W broadcast amortized; lowest measured L1-work: 96us)
// — the R15 kernel with a REGISTER DIET to reach 6 CTAs/SM (R15: 96 regs ->
// 5 CTAs -> occ 28%, L1 only 72% = latency-exposed, wall 133us).
// Diet: (1) W row consumed in two sequential halves reusing ONE set of 4
// 64-bit regs, enforced with asm volatile ld.shared.v2.b64 (no hoisting);
// (2) no 'cur' copy of the gather buffer (dup-movs made before reload).
// Everything else byte-identical to R15 (staging, tile, epilogue).
//
// Lane: pt = lane>>4 selects the point, q = lane&15 owns 4 contiguous
// channels [4q,4q+4) (= one guidance head, hd=q>>1) and ALL 16 w.
// Per k per warp: 1 zero-dup LDG.128 + 1 guid LDS + 4 ld.shared.v2.b64 W
// (2 distinct addrs, serves BOTH points) + 4 FMUL + 4 dup movs + 32 FFMA2.
__global__ void __launch_bounds__(128, 6)
pcf_kernel(const float* __restrict__ feat,
           const void*  __restrict__ inds_raw,
           const float* __restrict__ guid,
           const float* __restrict__ wn,
           float* __restrict__ out)
{
    // Per-warp 8KB blob:
    //  phase 1 (k-loop): [0,512) wn (pt-major 2x256), [512,784) guid (2x136)
    //                    [784,816) idx
    //  phase 2 (epilogue): whole 2048 floats = output bounce (2 pts x 1024)
    __shared__ __align__(16) float sblob[4][2048];

    const int wid  = threadIdx.x >> 5;
    const int lane = threadIdx.x & 31;
    const int pair = blockIdx.x * 4 + wid;      // point-pair id in [0, B*M/2)
    const int pt   = lane >> 4;                 // which point of the pair
    const int q    = lane & 15;                 // channel quad [4q, 4q+4)
    const int p    = pair * 2 + pt;
    const int b    = (p >= M_) ? 1 : 0;
    const int hd   = q >> 1;                    // guidance head of those 4 ch

    float* swn  = sblob[wid];                   // 512 floats (2 pts x 256)
    float* sgd  = sblob[wid] + 512;             // 2 x 136 (padded stride)
    int*   sidx = (int*)(sblob[wid] + 784);     // 32 ints
    float* sou  = sblob[wid];                   // 2048 floats (reused)

    // ---- per-warp staging: wn (2KB), guid (1KB), 32 indices ----
    {
        const float4* wsrc = (const float4*)(wn + (size_t)pair * 512);
        float4* wdst = (float4*)swn;
        #pragma unroll
        for (int r = 0; r < 4; r++)
            wdst[lane + r * 32] = __ldcs(wsrc + lane + r * 32);

        const float4* gsrc = (const float4*)(guid + (size_t)pair * 256);
        #pragma unroll
        for (int r = 0; r < 2; r++) {
            const int g   = lane + r * 32;      // 0..63 (32 float4 per point)
            const int gpt = g >> 5;
            const int off = g & 31;
            *(float4*)(sgd + gpt * 136 + off * 4) = __ldcs(gsrc + g);
        }
        long long idx;
        const size_t ioff = (size_t)pair * 32 + lane;
        if (g_idx_is64) idx = ((const long long*)inds_raw)[ioff];
        else            idx = (long long)((const int*)inds_raw)[ioff];
        sidx[lane] = (int)idx;
    }
    __syncwarp();

    const float* fb    = feat + (size_t)b * ((size_t)N_ * C_) + 4 * q;
    const float* mysgd = sgd + pt * 136;
    const int*   myidx = sidx + pt * K_;
    const uint32_t wsm = (uint32_t)__cvta_generic_to_shared(swn + pt * 256);

    unsigned long long acc[32];
    #pragma unroll
    for (int i = 0; i < 32; i++) acc[i] = 0ull;

    // depth-1 double buffer on the gather (one LDG.128 in flight)
    ulonglong2 A = *(const ulonglong2*)(fb + (size_t)myidx[0] * C_);

    #pragma unroll 4
    for (int k = 0; k < K_; k++) {
        // consume A into dup'd multipliers BEFORE reloading it
        const float g = mysgd[k * H_ + hd];
        const float2 f01 = *(const float2*)&A.x;
        const float2 f23 = *(const float2*)&A.y;
        const float m0 = f01.x * g, m1 = f01.y * g;
        const float m2 = f23.x * g, m3 = f23.y * g;
        unsigned long long d0, d1, d2, d3;
        asm("mov.b64 %0, {%1, %1};" : "=l"(d0) : "f"(m0));
        asm("mov.b64 %0, {%1, %1};" : "=l"(d1) : "f"(m1));
        asm("mov.b64 %0, {%1, %1};" : "=l"(d2) : "f"(m2));
        asm("mov.b64 %0, {%1, %1};" : "=l"(d3) : "f"(m3));

        if (k + 1 < K_)
            A = *(const ulonglong2*)(fb + (size_t)myidx[k + 1] * C_);

        // ---- W half 1: w-pairs 0..3 (ONE reg set, reused for half 2) ----
        unsigned long long W0, W1, W2, W3;
        asm volatile("ld.shared.v2.b64 {%0,%1}, [%2];"
                     : "=l"(W0), "=l"(W1) : "r"(wsm + (uint32_t)(k * 64)));
        asm volatile("ld.shared.v2.b64 {%0,%1}, [%2];"
                     : "=l"(W2), "=l"(W3) : "r"(wsm + (uint32_t)(k * 64 + 16)));
        asm("fma.rn.f32x2 %0, %1, %2, %3;" : "=l"(acc[ 0]) : "l"(d0), "l"(W0), "l"(acc[ 0]));
        asm("fma.rn.f32x2 %0, %1, %2, %3;" : "=l"(acc[ 1]) : "l"(d0), "l"(W1), "l"(acc[ 1]));
        asm("fma.rn.f32x2 %0, %1, %2, %3;" : "=l"(acc[ 2]) : "l"(d0), "l"(W2), "l"(acc[ 2]));
        asm("fma.rn.f32x2 %0, %1, %2, %3;" : "=l"(acc[ 3]) : "l"(d0), "l"(W3), "l"(acc[ 3]));
        asm("fma.rn.f32x2 %0, %1, %2, %3;" : "=l"(acc[ 8]) : "l"(d1), "l"(W0), "l"(acc[ 8]));
        asm("fma.rn.f32x2 %0, %1, %2, %3;" : "=l"(acc[ 9]) : "l"(d1), "l"(W1), "l"(acc[ 9]));
        asm("fma.rn.f32x2 %0, %1, %2, %3;" : "=l"(acc[10]) : "l"(d1), "l"(W2), "l"(acc[10]));
        asm("fma.rn.f32x2 %0, %1, %2, %3;" : "=l"(acc[11]) : "l"(d1), "l"(W3), "l"(acc[11]));
        asm("fma.rn.f32x2 %0, %1, %2, %3;" : "=l"(acc[16]) : "l"(d2), "l"(W0), "l"(acc[16]));
        asm("fma.rn.f32x2 %0, %1, %2, %3;" : "=l"(acc[17]) : "l"(d2), "l"(W1), "l"(acc[17]));
        asm("fma.rn.f32x2 %0, %1, %2, %3;" : "=l"(acc[18]) : "l"(d2), "l"(W2), "l"(acc[18]));
        asm("fma.rn.f32x2 %0, %1, %2, %3;" : "=l"(acc[19]) : "l"(d2), "l"(W3), "l"(acc[19]));
        asm("fma.rn.f32x2 %0, %1, %2, %3;" : "=l"(acc[24]) : "l"(d3), "l"(W0), "l"(acc[24]));
        asm("fma.rn.f32x2 %0, %1, %2, %3;" : "=l"(acc[25]) : "l"(d3), "l"(W1), "l"(acc[25]));
        asm("fma.rn.f32x2 %0, %1, %2, %3;" : "=l"(acc[26]) : "l"(d3), "l"(W2), "l"(acc[26]));
        asm("fma.rn.f32x2 %0, %1, %2, %3;" : "=l"(acc[27]) : "l"(d3), "l"(W3), "l"(acc[27]));

        // ---- W half 2: w-pairs 4..7 (same registers) ----
        asm volatile("ld.shared.v2.b64 {%0,%1}, [%2];"
                     : "=l"(W0), "=l"(W1) : "r"(wsm + (uint32_t)(k * 64 + 32)));
        asm volatile("ld.shared.v2.b64 {%0,%1}, [%2];"
                     : "=l"(W2), "=l"(W3) : "r"(wsm + (uint32_t)(k * 64 + 48)));
        asm("fma.rn.f32x2 %0, %1, %2, %3;" : "=l"(acc[ 4]) : "l"(d0), "l"(W0), "l"(acc[ 4]));
        asm("fma.rn.f32x2 %0, %1, %2, %3;" : "=l"(acc[ 5]) : "l"(d0), "l"(W1), "l"(acc[ 5]));
        asm("fma.rn.f32x2 %0, %1, %2, %3;" : "=l"(acc[ 6]) : "l"(d0), "l"(W2), "l"(acc[ 6]));
        asm("fma.rn.f32x2 %0, %1, %2, %3;" : "=l"(acc[ 7]) : "l"(d0), "l"(W3), "l"(acc[ 7]));
        asm("fma.rn.f32x2 %0, %1, %2, %3;" : "=l"(acc[12]) : "l"(d1), "l"(W0), "l"(acc[12]));
        asm("fma.rn.f32x2 %0, %1, %2, %3;" : "=l"(acc[13]) : "l"(d1), "l"(W1), "l"(acc[13]));
        asm("fma.rn.f32x2 %0, %1, %2, %3;" : "=l"(acc[14]) : "l"(d1), "l"(W2), "l"(acc[14]));
        asm("fma.rn.f32x2 %0, %1, %2, %3;" : "=l"(acc[15]) : "l"(d1), "l"(W3), "l"(acc[15]));
        asm("fma.rn.f32x2 %0, %1, %2, %3;" : "=l"(acc[20]) : "l"(d2), "l"(W0), "l"(acc[20]));
        asm("fma.rn.f32x2 %0, %1, %2, %3;" : "=l"(acc[21]) : "l"(d2), "l"(W1), "l"(acc[21]));
        asm("fma.rn.f32x2 %0, %1, %2, %3;" : "=l"(acc[22]) : "l"(d2), "l"(W2), "l"(acc[22]));
        asm("fma.rn.f32x2 %0, %1, %2, %3;" : "=l"(acc[23]) : "l"(d2), "l"(W3), "l"(acc[23]));
        asm("fma.rn.f32x2 %0, %1, %2, %3;" : "=l"(acc[28]) : "l"(d3), "l"(W0), "l"(acc[28]));
        asm("fma.rn.f32x2 %0, %1, %2, %3;" : "=l"(acc[29]) : "l"(d3), "l"(W1), "l"(acc[29]));
        asm("fma.rn.f32x2 %0, %1, %2, %3;" : "=l"(acc[30]) : "l"(d3), "l"(W2), "l"(acc[30]));
        asm("fma.rn.f32x2 %0, %1, %2, %3;" : "=l"(acc[31]) : "l"(d3), "l"(W3), "l"(acc[31]));
    }
    __syncwarp();   // done reading swn/sgd before the bounce reuses the blob

    // ---- epilogue: swizzled bounce. Lane region: pt*1024 + q*64 floats.
    // Chunk i = c_local*4 + jq holds out[4q+c_local][4jq .. +4) =
    // {acc[c_local*8+2jq], acc[c_local*8+2jq+1]}; stored at slot (i+q)&15.
    // Per quarter-warp all slot&7 distinct -> conflict-free.
    {
        float* sb = sou + pt * 1024 + q * 64;
        #pragma unroll
        for (int i = 0; i < 16; i++) {
            const int r  = i >> 2;               // c_local
            const int jq = i & 3;                // w quad
            const int s  = (i + q) & 15;         // swizzled slot
            *(ulonglong2*)(sb + s * 4) =
                make_ulonglong2(acc[r * 8 + 2 * jq], acc[r * 8 + 2 * jq + 1]);
        }
    }
    __syncwarp();
    // Coalesced flush of both points (2048 floats): flat = j*128 + lane*4.
    // Source: pt' = flat>>10; rem = flat&1023; c = rem>>4; w = rem&15;
    // q' = c>>2; i = (c&3)*4 + (w>>2); slot = (i+q')&15. Conflict-free.
    {
        float* o = out + (size_t)pair * 2048;
        #pragma unroll
        for (int j = 0; j < 16; j++) {
            const int flat = j * 128 + lane * 4;
            const int fpt  = flat >> 10;
            const int rem  = flat & 1023;
            const int c    = rem >> 4;
            const int w    = rem & 15;
            const int qq   = c >> 2;
            const int i    = (c & 3) * 4 + (w >> 2);
            const int s    = (i + qq) & 15;
            const float4 v = *(const float4*)(sou + fpt * 1024 + qq * 64 + s * 4);
            __stcs((float4*)(o + flat), v);
        }
    }
}

extern "C" void kernel_launch(void* const* d_in, const int* in_sizes, int n_in,
                              void* d_out, int out_size) {
    const float* feat = (const float*)d_in[0];
    const void*  inds = d_in[1];
    const float* guid = (const float*)d_in[2];
    const float* wn   = (const float*)d_in[3];
    float* out = (float*)d_out;

    detect_idx_kernel<<<1, 32>>>((const unsigned int*)inds);
    pcf_kernel<<<(B_ * M_) / 8, 128>>>(feat, inds, guid, wn, out);
}